// round 8
// baseline (speedup 1.0000x reference)
#include <cuda_runtime.h>

// CRF forward loss: B=1024, T=512, K=32.
// inputs (metadata order): emissions f32 [B,T,K], tags i32 [B,T],
//                          mask bool->int32 [B,T], transitions f32 [K,K]
// output: scalar f32 loss = mean_b( log_z - em_score - tr_score )
//
// Strategy: one warp per batch row; lane j owns state j.
//   Keep alpha as (scalar offset c, per-lane residual a, a[lane0]==0).
//   Precompute E[i][j] = exp(trans[i][j]) in registers (lane j holds column j).
//   Step:  p_i = exp(a_i);  s_j = sum_i p_i * E[i][j]  (shuffle-broadcast dot)
//          v_j = log(s_j) + em[t][j];  c += v_0;  a = v - v_0   (if mask[t])
//   em/tr path scores fused (shuffle the tag index; tr from smem).
//   Emissions prefetched 4 steps ahead; tags/mask 32 steps per coalesced load.
//
// R7 fix: mask buffer is int32 (bool promoted by the harness), not bytes.
//         Reading it as u8 made only t%4==0 steps active -> rel_err 0.75.

#define FULLM 0xffffffffu

constexpr int Bc = 1024;
constexpr int Tc = 512;
constexpr int Kc = 32;

__device__ float g_partial[Bc];

__global__ void __launch_bounds__(256, 1)
crf_forward(const float* __restrict__ em,
            const int* __restrict__ tags,
            const int* __restrict__ mask,
            const float* __restrict__ trans)
{
    __shared__ float tr_s[Kc * Kc];

    const int lane = threadIdx.x & 31;
    const int wid  = threadIdx.x >> 5;

    // stage raw transitions in smem (needed for tr_score lookups)
    for (int i = threadIdx.x; i < Kc * Kc; i += blockDim.x)
        tr_s[i] = trans[i];
    __syncthreads();

    const int b = blockIdx.x * 8 + wid;

    // lane j holds column j of E = exp(transitions)
    float E[Kc];
#pragma unroll
    for (int i = 0; i < Kc; i++)
        E[i] = __expf(tr_s[i * Kc + lane]);

    const float* emB = em   + (size_t)b * Tc * Kc;
    const int*   tgB = tags + (size_t)b * Tc;
    const int*   mB  = mask + (size_t)b * Tc;

    // prefetch ring: em rows for t .. t+3 (per lane one float each)
    float nxt0 = emB[0 * Kc + lane];
    float nxt1 = emB[1 * Kc + lane];
    float nxt2 = emB[2 * Kc + lane];
    float nxt3 = emB[3 * Kc + lane];

    float a, cacc;
    float escore = 0.f, tscore = 0.f;
    int   tp;

    // ---- t = 0 peel: alpha0 = em[0]; em_score += mask[0] * em[0][tag0] ----
    {
        int  tag0 = tgB[0];          // uniform broadcast load
        bool m0   = mB[0] != 0;
        float v0  = __shfl_sync(FULLM, nxt0, 0);
        cacc = v0;
        a    = nxt0 - v0;            // a[0] == 0
        float emtag = __shfl_sync(FULLM, nxt0, tag0);
        if (m0) escore += emtag;
        tp = tag0;
    }

    for (int ch = 0; ch < Tc / 32; ch++) {
        // one coalesced load of 32 tags + 32 mask words per chunk
        int tg32 = tgB[ch * 32 + lane];
        int mk32 = mB[ch * 32 + lane];

        for (int jj = 0; jj < 32; jj += 4) {
            float c0 = nxt0, c1 = nxt1, c2 = nxt2, c3 = nxt3;
            const int tb = ch * 32 + jj;
            // prefetch em rows for t+4..t+7 (clamped at T-1; harmless reload)
            int t4 = min(tb + 4, Tc - 1);
            int t5 = min(tb + 5, Tc - 1);
            int t6 = min(tb + 6, Tc - 1);
            int t7 = min(tb + 7, Tc - 1);
            nxt0 = emB[t4 * Kc + lane];
            nxt1 = emB[t5 * Kc + lane];
            nxt2 = emB[t6 * Kc + lane];
            nxt3 = emB[t7 * Kc + lane];

            float curA[4] = {c0, c1, c2, c3};
#pragma unroll
            for (int q = 0; q < 4; q++) {
                const int t   = tb + q;
                float     emv = curA[q];
                int tg = __shfl_sync(FULLM, tg32, jj + q);
                int m  = __shfl_sync(FULLM, mk32, jj + q);
                float emtag = __shfl_sync(FULLM, emv, tg);

                if (t != 0) {
                    float p  = __expf(a);
                    float s0 = 0.f, s1 = 0.f, s2 = 0.f, s3 = 0.f;
#pragma unroll
                    for (int i = 0; i < Kc; i += 4) {
                        s0 = fmaf(__shfl_sync(FULLM, p, i + 0), E[i + 0], s0);
                        s1 = fmaf(__shfl_sync(FULLM, p, i + 1), E[i + 1], s1);
                        s2 = fmaf(__shfl_sync(FULLM, p, i + 2), E[i + 2], s2);
                        s3 = fmaf(__shfl_sync(FULLM, p, i + 3), E[i + 3], s3);
                    }
                    float s = (s0 + s1) + (s2 + s3);
                    float v = __logf(s) + emv;
                    if (m) {
                        escore += emtag;
                        tscore += tr_s[tp * Kc + tg];   // uniform broadcast LDS
                        float v0 = __shfl_sync(FULLM, v, 0);
                        cacc += v0;
                        a = v - v0;                     // renormalize: a[0]=0
                    }
                }
                tp = tg;   // tags advance regardless of mask (matches ref)
            }
        }
    }

    // ---- final logsumexp over states ----
    float amax = a;
#pragma unroll
    for (int o = 16; o; o >>= 1)
        amax = fmaxf(amax, __shfl_xor_sync(FULLM, amax, o));
    float es = __expf(a - amax);
#pragma unroll
    for (int o = 16; o; o >>= 1)
        es += __shfl_xor_sync(FULLM, es, o);
    float logz = cacc + amax + __logf(es);

    if (lane == 0)
        g_partial[b] = logz - escore - tscore;
}

__global__ void __launch_bounds__(256)
crf_reduce(float* __restrict__ out)
{
    __shared__ float sh[8];
    int tid = threadIdx.x;
    float s = 0.f;
    for (int i = tid; i < Bc; i += 256)
        s += g_partial[i];
#pragma unroll
    for (int o = 16; o; o >>= 1)
        s += __shfl_xor_sync(FULLM, s, o);
    if ((tid & 31) == 0) sh[tid >> 5] = s;
    __syncthreads();
    if (tid < 32) {
        float v = (tid < 8) ? sh[tid] : 0.f;
#pragma unroll
        for (int o = 4; o; o >>= 1)
            v += __shfl_xor_sync(FULLM, v, o);
        if (tid == 0) out[0] = v * (1.0f / (float)Bc);
    }
}

extern "C" void kernel_launch(void* const* d_in, const int* in_sizes, int n_in,
                              void* d_out, int out_size)
{
    const float* em    = (const float*)d_in[0];
    const int*   tags  = (const int*)d_in[1];
    const int*   mask  = (const int*)d_in[2];
    const float* trans = (const float*)d_in[3];
    float*       out   = (float*)d_out;

    crf_forward<<<Bc / 8, 256>>>(em, tags, mask, trans);
    crf_reduce<<<1, 256>>>(out);
}